// round 15
// baseline (speedup 1.0000x reference)
#include <cuda_runtime.h>
#include <cstdint>

#define N_NODES 50000
#define DIM     64
#define CHUNKS  (DIM / 4)    // 16 float4 per row
#define TPE     8            // 8 threads per edge-slot: full 128B line coalescing
#define EPT_G   2            // edges per thread in gather (measured optimum)

// Accumulator [N_NODES, 16] float4 = 12.8 MB (L2-resident), 16B-aligned by type.
__device__ float4 g_Mv[(size_t)N_NODES * CHUNKS];

__device__ __forceinline__ long long load_idx(const void* base, long long i, int is64) {
    if (is64) return __ldg(((const long long*)base) + i);
    return (long long)__ldg(((const int*)base) + i);
}

__device__ __forceinline__ long long bcast8(long long v) {
    return __shfl_sync(0xFFFFFFFFu, v, 0, 8);
}

// Per-block dtype probe (thread 0 checks 8 entries, broadcast via shared).
__device__ __forceinline__ int probe_is64(const void* rev, int E) {
    __shared__ int sh_is64;
    if (threadIdx.x == 0) {
        const long long* r64 = (const long long*)rev;
        int ok = 1;
        #pragma unroll
        for (int k = 0; k < 8; k++) {
            long long v = r64[k];
            if (v < 0 || v >= (long long)E) { ok = 0; break; }
        }
        sh_is64 = ok;
    }
    __syncthreads();
    return sh_is64;
}

__device__ __forceinline__ void red4(float4* p, float4 v) {
    asm volatile("red.global.add.v4.f32 [%0], {%1, %2, %3, %4};"
        :: "l"(__cvta_generic_to_global(p)),
           "f"(v.x), "f"(v.y), "f"(v.z), "f"(v.w) : "memory");
}

// ---------------------------------------------------------------------------
// Kernel 1: scatter-add — R14 measured-best config.
// 1 edge per 8-thread slot, 2 chunks each. M loads hoisted BEFORE the index
// broadcast (decouples the streaming fills from the shuffle dependency).
// __ldcs evict-first protects the L2-resident M_v accumulator.
// red.global.add.v4.f32 = one 16B L2-side reduction per chunk.
// ---------------------------------------------------------------------------
__global__ void scatter_kernel(const float4* __restrict__ M4,
                               const void* __restrict__ ei,
                               const void* __restrict__ rev,
                               int E) {
    int is64 = probe_is64(rev, E);

    int t = blockIdx.x * blockDim.x + threadIdx.x;
    int e = t >> 3;
    int c = t & 7;
    if (e >= E) return;

    const float4* mrow = M4 + (size_t)e * CHUNKS;
    float4 v0 = __ldcs(&mrow[c]);
    float4 v1 = __ldcs(&mrow[c + 8]);

    long long d = 0;
    if (c == 0) d = load_idx(ei, (long long)E + e, is64);   // dest
    d = bcast8(d);

    float4* prow = g_Mv + (size_t)d * CHUNKS;
    red4(prow + c, v0);
    red4(prow + c + 8, v1);
}

// ---------------------------------------------------------------------------
// Kernel 2: out[e] = M_v[src[e]] - M[rev[e]] — R13 measured-best config.
// 8 threads/edge-slot, 2 edges/thread, natural regs=40 keep all 8
// front-batched loads live. M_v/M: __ldg. out: __stcs (write-once).
// ---------------------------------------------------------------------------
__global__ void gather_kernel(const float4* __restrict__ M4,
                              const void* __restrict__ ei,
                              const void* __restrict__ rev,
                              float4* __restrict__ out,
                              int E) {
    int is64 = probe_is64(rev, E);

    int t = blockIdx.x * blockDim.x + threadIdx.x;
    long long e0 = (long long)(t >> 3) * EPT_G;
    long long e1 = e0 + 1;
    int c = t & 7;
    if (e0 >= E) return;
    bool p1 = e1 < E;

    long long s0 = 0, r0 = 0, s1 = 0, r1 = 0;
    if (c == 0) {
        s0 = load_idx(ei, e0, is64);
        r0 = load_idx(rev, e0, is64);
        if (p1) {
            s1 = load_idx(ei, e1, is64);
            r1 = load_idx(rev, e1, is64);
        }
    }
    s0 = bcast8(s0); r0 = bcast8(r0);
    s1 = bcast8(s1); r1 = bcast8(r1);

    const float4* arow0 = g_Mv + (size_t)s0 * CHUNKS;
    const float4* brow0 = M4 + (size_t)r0 * CHUNKS;

    float4 a00 = __ldg(&arow0[c]);
    float4 a01 = __ldg(&arow0[c + 8]);
    float4 b00 = __ldg(&brow0[c]);
    float4 b01 = __ldg(&brow0[c + 8]);

    float4 a10, a11, b10, b11;
    if (p1) {
        const float4* arow1 = g_Mv + (size_t)s1 * CHUNKS;
        const float4* brow1 = M4 + (size_t)r1 * CHUNKS;
        a10 = __ldg(&arow1[c]);
        a11 = __ldg(&arow1[c + 8]);
        b10 = __ldg(&brow1[c]);
        b11 = __ldg(&brow1[c + 8]);
    }

    float4 o;
    float4* orow0 = out + (size_t)e0 * CHUNKS;
    o.x = a00.x - b00.x; o.y = a00.y - b00.y; o.z = a00.z - b00.z; o.w = a00.w - b00.w;
    __stcs(&orow0[c], o);
    o.x = a01.x - b01.x; o.y = a01.y - b01.y; o.z = a01.z - b01.z; o.w = a01.w - b01.w;
    __stcs(&orow0[c + 8], o);

    if (p1) {
        float4* orow1 = out + (size_t)e1 * CHUNKS;
        o.x = a10.x - b10.x; o.y = a10.y - b10.y; o.z = a10.z - b10.z; o.w = a10.w - b10.w;
        __stcs(&orow1[c], o);
        o.x = a11.x - b11.x; o.y = a11.y - b11.y; o.z = a11.z - b11.z; o.w = a11.w - b11.w;
        __stcs(&orow1[c + 8], o);
    }
}

// ---------------------------------------------------------------------------
// Launcher. Inputs (metadata order):
//   d_in[0] = M          float32     [E, 64]
//   d_in[1] = edge_index int64/int32 [2, E]  (row0=src, row1=dest)
//   d_in[2] = rev_index  int64/int32 [E]
//   d_in[3] = dim_size   scalar (50000, unused)
// Output: float32 [E, 64]
// ---------------------------------------------------------------------------
extern "C" void kernel_launch(void* const* d_in, const int* in_sizes, int n_in,
                              void* d_out, int out_size) {
    const float4* M4   = (const float4*)d_in[0];
    const void*   ei   = d_in[1];
    const void*   rev  = d_in[2];
    float4*       out4 = (float4*)d_out;

    const int E = in_sizes[2];

    void* mv_ptr = nullptr;
    cudaGetSymbolAddress(&mv_ptr, g_Mv);
    cudaMemsetAsync(mv_ptr, 0, (size_t)N_NODES * CHUNKS * sizeof(float4));

    {
        long long threads = (long long)E * TPE;       // 1 edge per slot
        int tpb = 256;
        int blocks = (int)((threads + tpb - 1) / tpb);
        scatter_kernel<<<blocks, tpb>>>(M4, ei, rev, E);
    }
    {
        long long slots = ((long long)E + EPT_G - 1) / EPT_G;
        long long threads = slots * TPE;
        int tpb = 256;
        int blocks = (int)((threads + tpb - 1) / tpb);
        gather_kernel<<<blocks, tpb>>>(M4, ei, rev, out4, E);
    }
}

// round 17
// speedup vs baseline: 1.0021x; 1.0021x over previous
#include <cuda_runtime.h>
#include <cstdint>

#define N_NODES 50000
#define DIM     64
#define CHUNKS  (DIM / 4)    // 16 float4 per row
#define TPE     8            // 8 threads per edge-slot: full 128B line coalescing
#define EPT_G   2            // edges per thread in gather (measured optimum)

// Accumulator [N_NODES, 16] float4 = 12.8 MB (L2-resident), 16B-aligned by type.
__device__ float4 g_Mv[(size_t)N_NODES * CHUNKS];

__device__ __forceinline__ long long load_idx(const void* base, long long i, int is64) {
    if (is64) return __ldg(((const long long*)base) + i);
    return (long long)__ldg(((const int*)base) + i);
}

__device__ __forceinline__ long long bcast8(long long v) {
    return __shfl_sync(0xFFFFFFFFu, v, 0, 8);
}

// Per-block dtype probe (thread 0 checks 8 entries, broadcast via shared).
__device__ __forceinline__ int probe_is64(const void* rev, int E) {
    __shared__ int sh_is64;
    if (threadIdx.x == 0) {
        const long long* r64 = (const long long*)rev;
        int ok = 1;
        #pragma unroll
        for (int k = 0; k < 8; k++) {
            long long v = r64[k];
            if (v < 0 || v >= (long long)E) { ok = 0; break; }
        }
        sh_is64 = ok;
    }
    __syncthreads();
    return sh_is64;
}

__device__ __forceinline__ void red4(float4* p, float4 v) {
    asm volatile("red.global.add.v4.f32 [%0], {%1, %2, %3, %4};"
        :: "l"(__cvta_generic_to_global(p)),
           "f"(v.x), "f"(v.y), "f"(v.z), "f"(v.w) : "memory");
}

// ---------------------------------------------------------------------------
// Kernel 1: scatter-add (measured-best config, R14).
// 1 edge per 8-thread slot, 2 chunks each. M loads hoisted BEFORE the index
// broadcast (decouples streaming fills from the shuffle dependency chain).
// __ldcs evict-first protects the L2-resident M_v accumulator.
// red.global.add.v4.f32 = one 16B L2-side reduction per chunk.
// ---------------------------------------------------------------------------
__global__ void scatter_kernel(const float4* __restrict__ M4,
                               const void* __restrict__ ei,
                               const void* __restrict__ rev,
                               int E) {
    int is64 = probe_is64(rev, E);

    int t = blockIdx.x * blockDim.x + threadIdx.x;
    int e = t >> 3;
    int c = t & 7;
    if (e >= E) return;

    const float4* mrow = M4 + (size_t)e * CHUNKS;
    float4 v0 = __ldcs(&mrow[c]);
    float4 v1 = __ldcs(&mrow[c + 8]);

    long long d = 0;
    if (c == 0) d = load_idx(ei, (long long)E + e, is64);   // dest
    d = bcast8(d);

    float4* prow = g_Mv + (size_t)d * CHUNKS;
    red4(prow + c, v0);
    red4(prow + c + 8, v1);
}

// ---------------------------------------------------------------------------
// Kernel 2: out[e] = M_v[src[e]] - M[rev[e]] (measured-best config, R13/R14).
// 8 threads/edge-slot, 2 edges/thread, natural regs=40 keep all 8
// front-batched loads live (capping to 32 spills: -5us, measured R9;
// EPT=4 overwhelms the allocator: -10us, measured R12).
// M[rev] DRAM loads issued before L2-hit M_v loads. out: __stcs.
// ---------------------------------------------------------------------------
__global__ void gather_kernel(const float4* __restrict__ M4,
                              const void* __restrict__ ei,
                              const void* __restrict__ rev,
                              float4* __restrict__ out,
                              int E) {
    int is64 = probe_is64(rev, E);

    int t = blockIdx.x * blockDim.x + threadIdx.x;
    long long e0 = (long long)(t >> 3) * EPT_G;
    long long e1 = e0 + 1;
    int c = t & 7;
    if (e0 >= E) return;
    bool p1 = e1 < E;

    long long s0 = 0, r0 = 0, s1 = 0, r1 = 0;
    if (c == 0) {
        r0 = load_idx(rev, e0, is64);
        s0 = load_idx(ei, e0, is64);
        if (p1) {
            r1 = load_idx(rev, e1, is64);
            s1 = load_idx(ei, e1, is64);
        }
    }
    r0 = bcast8(r0); s0 = bcast8(s0);
    r1 = bcast8(r1); s1 = bcast8(s1);

    const float4* brow0 = M4 + (size_t)r0 * CHUNKS;
    const float4* brow1 = M4 + (size_t)r1 * CHUNKS;
    const float4* arow0 = g_Mv + (size_t)s0 * CHUNKS;
    const float4* arow1 = g_Mv + (size_t)s1 * CHUNKS;

    // DRAM-bound loads first
    float4 b00 = __ldg(&brow0[c]);
    float4 b01 = __ldg(&brow0[c + 8]);
    float4 b10, b11;
    if (p1) {
        b10 = __ldg(&brow1[c]);
        b11 = __ldg(&brow1[c + 8]);
    }
    // L2-hit loads second (overlap the DRAM shadow)
    float4 a00 = __ldg(&arow0[c]);
    float4 a01 = __ldg(&arow0[c + 8]);
    float4 a10, a11;
    if (p1) {
        a10 = __ldg(&arow1[c]);
        a11 = __ldg(&arow1[c + 8]);
    }

    float4 o;
    float4* orow0 = out + (size_t)e0 * CHUNKS;
    o.x = a00.x - b00.x; o.y = a00.y - b00.y; o.z = a00.z - b00.z; o.w = a00.w - b00.w;
    __stcs(&orow0[c], o);
    o.x = a01.x - b01.x; o.y = a01.y - b01.y; o.z = a01.z - b01.z; o.w = a01.w - b01.w;
    __stcs(&orow0[c + 8], o);

    if (p1) {
        float4* orow1 = out + (size_t)e1 * CHUNKS;
        o.x = a10.x - b10.x; o.y = a10.y - b10.y; o.z = a10.z - b10.z; o.w = a10.w - b10.w;
        __stcs(&orow1[c], o);
        o.x = a11.x - b11.x; o.y = a11.y - b11.y; o.z = a11.z - b11.z; o.w = a11.w - b11.w;
        __stcs(&orow1[c + 8], o);
    }
}

// ---------------------------------------------------------------------------
// Launcher (single stream, graph-capturable, allocation-free).
// Inputs (metadata order):
//   d_in[0] = M          float32     [E, 64]
//   d_in[1] = edge_index int64/int32 [2, E]  (row0=src, row1=dest)
//   d_in[2] = rev_index  int64/int32 [E]
//   d_in[3] = dim_size   scalar (50000, unused)
// Output: float32 [E, 64]
// ---------------------------------------------------------------------------
extern "C" void kernel_launch(void* const* d_in, const int* in_sizes, int n_in,
                              void* d_out, int out_size) {
    const float4* M4   = (const float4*)d_in[0];
    const void*   ei   = d_in[1];
    const void*   rev  = d_in[2];
    float4*       out4 = (float4*)d_out;

    const int E = in_sizes[2];

    void* mv_ptr = nullptr;
    cudaGetSymbolAddress(&mv_ptr, g_Mv);
    cudaMemsetAsync(mv_ptr, 0, (size_t)N_NODES * CHUNKS * sizeof(float4));

    {
        long long threads = (long long)E * TPE;       // 1 edge per slot
        int tpb = 256;
        int blocks = (int)((threads + tpb - 1) / tpb);
        scatter_kernel<<<blocks, tpb>>>(M4, ei, rev, E);
    }
    {
        long long slots = ((long long)E + EPT_G - 1) / EPT_G;
        long long threads = slots * TPE;
        int tpb = 256;
        int blocks = (int)((threads + tpb - 1) / tpb);
        gather_kernel<<<blocks, tpb>>>(M4, ei, rev, out4, E);
    }
}